// round 15
// baseline (speedup 1.0000x reference)
#include <cuda_runtime.h>
#include <cuda_fp16.h>
#include <cstdint>

// Problem constants
#define HH     1024
#define BB     4
#define SS     1024
#define NHEADS 16
#define DHEAD  64
#define MTOT   (BB * SS)

// fp16 copies of GEMM inputs.
__device__ __align__(16) __half g_xh[3][(size_t)MTOT * HH];
__device__ __align__(16) __half g_wh[3][(size_t)HH * HH];

// GEMM outputs for attention: Q (pre-scaled by 0.125*log2e), K, V in fp16.
__device__ __align__(16) __half g_qh[(size_t)MTOT * HH];
__device__ __align__(16) __half g_kh[(size_t)MTOT * HH];
__device__ __align__(16) __half g_vh[(size_t)MTOT * HH];

#define SCLQ 0.18033688f   // 0.125 * log2(e)

// ---------------------------------------------------------------------------
// helpers
// ---------------------------------------------------------------------------
static __device__ __forceinline__ uint32_t smem_u32(const void* p) {
    uint32_t a;
    asm("{ .reg .u64 t; cvta.to.shared.u64 t, %1; cvt.u32.u64 %0, t; }"
        : "=r"(a) : "l"(p));
    return a;
}
static __device__ __forceinline__ uint32_t pack2h(float x, float y) {
    __half2 h = __floats2half2_rn(x, y);
    return *reinterpret_cast<uint32_t*>(&h);
}
static __device__ __forceinline__ float2 unpack2h(uint32_t u) {
    __half2 h = *reinterpret_cast<__half2*>(&u);
    return __half22float2(h);
}
static __device__ __forceinline__ void cp16(uint32_t saddr, const void* g) {
    asm volatile("cp.async.cg.shared.global [%0], [%1], 16;"
                 :: "r"(saddr), "l"(g) : "memory");
}
#define CP_COMMIT() asm volatile("cp.async.commit_group;" ::: "memory")

static __device__ __forceinline__ void mma_f16(float* c, const uint32_t* a, const uint32_t* b) {
    asm volatile(
        "mma.sync.aligned.m16n8k16.row.col.f32.f16.f16.f32 "
        "{%0,%1,%2,%3}, {%4,%5,%6,%7}, {%8,%9}, {%0,%1,%2,%3};"
        : "+f"(c[0]), "+f"(c[1]), "+f"(c[2]), "+f"(c[3])
        : "r"(a[0]), "r"(a[1]), "r"(a[2]), "r"(a[3]), "r"(b[0]), "r"(b[1]));
}
// fp16-accumulate variant (QK^T only — logits small, 4 k-steps)
static __device__ __forceinline__ void mma_f16h(uint32_t* c, const uint32_t* a, const uint32_t* b) {
    asm volatile(
        "mma.sync.aligned.m16n8k16.row.col.f16.f16.f16.f16 "
        "{%0,%1}, {%2,%3,%4,%5}, {%6,%7}, {%0,%1};"
        : "+r"(c[0]), "+r"(c[1])
        : "r"(a[0]), "r"(a[1]), "r"(a[2]), "r"(a[3]), "r"(b[0]), "r"(b[1]));
}
static __device__ __forceinline__ void ldsm4(uint32_t* r, uint32_t saddr) {
    asm volatile("ldmatrix.sync.aligned.m8n8.x4.shared.b16 {%0,%1,%2,%3}, [%4];"
                 : "=r"(r[0]), "=r"(r[1]), "=r"(r[2]), "=r"(r[3]) : "r"(saddr));
}
static __device__ __forceinline__ void ldsm4t(uint32_t* r, uint32_t saddr) {
    asm volatile("ldmatrix.sync.aligned.m8n8.x4.trans.shared.b16 {%0,%1,%2,%3}, [%4];"
                 : "=r"(r[0]), "=r"(r[1]), "=r"(r[2]), "=r"(r[3]) : "r"(saddr));
}
static __device__ __forceinline__ float ex2(float x) {
    float y; asm("ex2.approx.f32 %0, %1;" : "=f"(y) : "f"(x)); return y;
}

// ---------------------------------------------------------------------------
// fp32 -> fp16 convert for ONE projection's X and W, flat grid.
// ---------------------------------------------------------------------------
__global__ void convert_pair(const float4* __restrict__ X, const float4* __restrict__ W,
                             int mat, int n4x, int n4w)
{
    const int i = blockIdx.x * 256 + threadIdx.x;
    if (i < n4x) {
        float4 v = X[i];
        ((uint2*)g_xh[mat])[i] = make_uint2(pack2h(v.x, v.y), pack2h(v.z, v.w));
    } else {
        const int j = i - n4x;
        if (j < n4w) {
            float4 v = W[j];
            ((uint2*)g_wh[mat])[j] = make_uint2(pack2h(v.x, v.y), pack2h(v.z, v.w));
        }
    }
}

// ---------------------------------------------------------------------------
// Tensor-core GEMM (fp16, fp32 acc) — R13 CHAMPION, byte-identical mainloop:
// CTA 128x128, 8 warps (2M x 4N), K staged 64, triple-buffered cp.async ring,
// one __syncthreads per stage. bn0 = column offset (quarter-N launches).
// ---------------------------------------------------------------------------
#define GST     144
#define GTILE   (128 * GST)
#define GSTAGE  (2 * GTILE)
#define GNST    (HH / 64)
#define GEMM_SMEM (3 * GSTAGE)

__global__ void __launch_bounds__(256, 2) gemm_mma(
    const float* __restrict__ bias, int mat, int bn0)
{
    extern __shared__ char smc[];

    const int tid  = threadIdx.x;
    const int lane = tid & 31;
    const int wid  = tid >> 5;
    const int wm   = wid & 1;
    const int wn   = wid >> 1;
    const int bm   = blockIdx.y * 128;
    const int bn   = bn0 + blockIdx.x * 128;

    const __half* Ah = g_xh[mat] + (size_t)bm * HH;
    const __half* Bh = g_wh[mat] + (size_t)bn * HH;

    const uint32_t smem_base = smem_u32(smc);

    auto issue_stage = [&](int s, int buf) {
        const uint32_t sb = smem_base + (uint32_t)buf * GSTAGE;
        const int k0 = s * 64;
#pragma unroll
        for (int i = 0; i < 4; i++) {
            const int idx = tid + i * 256;
            const int row = idx >> 3;
            const int q   = idx & 7;
            const uint32_t so = (uint32_t)(row * GST + q * 16);
            const size_t   go = (size_t)row * HH + k0 + q * 8;
            cp16(sb + so, Ah + go);
            cp16(sb + GTILE + so, Bh + go);
        }
    };

    float acc[4][4][4];
#pragma unroll
    for (int i = 0; i < 4; i++)
#pragma unroll
        for (int j = 0; j < 4; j++)
#pragma unroll
            for (int k = 0; k < 4; k++) acc[i][j][k] = 0.f;

    issue_stage(0, 0); CP_COMMIT();
    issue_stage(1, 1); CP_COMMIT();

    const int arow = wm * 64 + ((lane >> 3) & 1) * 8 + (lane & 7);
    const int acol = (lane >> 4) * 8;
    const int brow = wn * 32 + (lane & 15);
    const int bcol = (lane >> 4) * 8;

    int cur = 0;
    for (int s = 0; s < GNST; s++) {
        if (s + 1 < GNST) { asm volatile("cp.async.wait_group 1;" ::: "memory"); }
        else              { asm volatile("cp.async.wait_group 0;" ::: "memory"); }
        __syncthreads();

        if (s + 2 < GNST) {
            int nb = cur + 2; if (nb >= 3) nb -= 3;
            issue_stage(s + 2, nb);
            CP_COMMIT();
        }

        const uint32_t sA = smem_base + (uint32_t)cur * GSTAGE;
        const uint32_t sB = sA + GTILE;

#pragma unroll
        for (int t = 0; t < 4; t++) {
            uint32_t Af[4][4], Bf[4][2];
#pragma unroll
            for (int mf = 0; mf < 4; mf++)
                ldsm4(Af[mf], sA + (arow + mf * 16) * GST + (t * 16 + acol) * 2);
#pragma unroll
            for (int np = 0; np < 2; np++) {
                uint32_t kh[4];
                ldsm4(kh, sB + (brow + np * 16) * GST + (t * 16 + bcol) * 2);
                Bf[2 * np][0]     = kh[0]; Bf[2 * np][1]     = kh[2];
                Bf[2 * np + 1][0] = kh[1]; Bf[2 * np + 1][1] = kh[3];
            }
#pragma unroll
            for (int mf = 0; mf < 4; mf++)
#pragma unroll
                for (int nf = 0; nf < 4; nf++)
                    mma_f16(acc[mf][nf], Af[mf], Bf[nf]);
        }

        cur = (cur + 1 == 3) ? 0 : cur + 1;
    }

    const float sc = (mat == 0) ? SCLQ : 1.0f;
    uint32_t* ph = (mat == 0) ? (uint32_t*)g_qh : ((mat == 1) ? (uint32_t*)g_kh : (uint32_t*)g_vh);

#pragma unroll
    for (int nf = 0; nf < 4; nf++) {
        const int col = bn + wn * 32 + nf * 8 + (lane & 3) * 2;
        const float2 bs = *(const float2*)&bias[col];
#pragma unroll
        for (int mf = 0; mf < 4; mf++) {
            const int row0 = bm + wm * 64 + mf * 16 + (lane >> 2);
            float v0 = fmaxf(acc[mf][nf][0] + bs.x, 0.f) * sc;
            float v1 = fmaxf(acc[mf][nf][1] + bs.y, 0.f) * sc;
            float v2 = fmaxf(acc[mf][nf][2] + bs.x, 0.f) * sc;
            float v3 = fmaxf(acc[mf][nf][3] + bs.y, 0.f) * sc;
            ph[((size_t)row0 * HH + col) >> 1]       = pack2h(v0, v1);
            ph[((size_t)(row0 + 8) * HH + col) >> 1] = pack2h(v2, v3);
        }
    }
}

// ---------------------------------------------------------------------------
// Tensor-core flash attention — R13 champion, byte-identical mainloop:
// max-free softmax, kv-tile 64, fp16-acc QK^T (bit-exact repack), fp32-acc
// PV, deferred l-reduction, 4 CTA/SM. n0 = head offset (quarter launches).
// ---------------------------------------------------------------------------
#define QB      64
#define KRST    144
#define KVT     64
#define KVOFF   (KVT * KRST)
#define KBUF    (2 * KVOFF)
#define ATT_SMEM (2 * KBUF)
#define NKV     (SS / KVT)

__global__ void __launch_bounds__(128, 4) attn_tc(
    const float* __restrict__ masks,
    const float* __restrict__ query,
    float* __restrict__ out,
    int n0)
{
    extern __shared__ char sma[];
    const uint32_t smb = smem_u32(sma);

    const int b    = blockIdx.z;
    const int n    = n0 + blockIdx.y;
    const int q0   = blockIdx.x * QB;
    const int tid  = threadIdx.x;
    const int lane = tid & 31;
    const int wid  = tid >> 5;
    const int hc   = n * DHEAD;

#pragma unroll
    for (int i = 0; i < 4; i++) {
        const int idx = tid + i * 128;
        const int row = idx >> 3, qq = idx & 7;
        cp16(smb + row * KRST + qq * 16,
             g_qh + (size_t)(b * SS + q0 + row) * HH + hc + qq * 8);
    }
    CP_COMMIT();
    asm volatile("cp.async.wait_group 0;" ::: "memory");
    __syncthreads();

    uint32_t qh[4][4];
    {
        const int arow = wid * 16 + ((lane >> 3) & 1) * 8 + (lane & 7);
        const int acol = (lane >> 4) * 8;
#pragma unroll
        for (int t = 0; t < 4; t++)
            ldsm4(qh[t], smb + arow * KRST + (16 * t + acol) * 2);
    }
    __syncthreads();

    auto issue_kv = [&](int s) {
        const uint32_t sb = smb + (uint32_t)((s & 1) * KBUF);
        const size_t tokbase = (size_t)(b * SS + s * KVT);
#pragma unroll
        for (int i = 0; i < 4; i++) {
            const int idx = tid + i * 128;
            const int row = idx >> 3, qq = idx & 7;
            const uint32_t soff = row * KRST + qq * 16;
            const size_t goff = (tokbase + row) * HH + hc + qq * 8;
            cp16(sb + soff, g_kh + goff);
            cp16(sb + KVOFF + soff, g_vh + goff);
        }
    };
    issue_kv(0); CP_COMMIT();
    issue_kv(1); CP_COMMIT();

    float O[8][4];
    float l0 = 0.f, l1 = 0.f;
#pragma unroll
    for (int i = 0; i < 8; i++)
#pragma unroll
        for (int j = 0; j < 4; j++) O[i][j] = 0.f;

    const int brow = lane & 15;
    const int bcol = (lane >> 4) * 8;

    for (int kb = 0; kb < NKV; kb++) {
        if (kb + 1 < NKV) { asm volatile("cp.async.wait_group 1;" ::: "memory"); }
        else              { asm volatile("cp.async.wait_group 0;" ::: "memory"); }
        __syncthreads();

        const uint32_t sb = smb + (uint32_t)((kb & 1) * KBUF);

        uint32_t Sh[8][2];
#pragma unroll
        for (int i = 0; i < 8; i++) { Sh[i][0] = 0u; Sh[i][1] = 0u; }

#pragma unroll
        for (int t = 0; t < 4; t++) {
#pragma unroll
            for (int j = 0; j < 4; j++) {
                uint32_t kh[4], bf[2];
                ldsm4(kh, sb + (16 * j + brow) * KRST + (16 * t + bcol) * 2);
                bf[0] = kh[0]; bf[1] = kh[2];
                mma_f16h(Sh[2 * j], qh[t], bf);
                bf[0] = kh[1]; bf[1] = kh[3];
                mma_f16h(Sh[2 * j + 1], qh[t], bf);
            }
        }

#pragma unroll
        for (int i = 0; i < 8; i++) {
            float2 a = unpack2h(Sh[i][0]);
            float2 c = unpack2h(Sh[i][1]);
            float e0 = ex2(a.x), e1 = ex2(a.y);
            float e2 = ex2(c.x), e3 = ex2(c.y);
            l0 += e0 + e1;
            l1 += e2 + e3;
            Sh[i][0] = pack2h(e0, e1);
            Sh[i][1] = pack2h(e2, e3);
        }

#pragma unroll
        for (int i = 0; i < 4; i++) {
            uint32_t Pa4[4] = {Sh[2 * i][0], Sh[2 * i][1],
                               Sh[2 * i + 1][0], Sh[2 * i + 1][1]};
#pragma unroll
            for (int t4 = 0; t4 < 4; t4++) {
                uint32_t v[4];
                ldsm4t(v, sb + KVOFF + (16 * i + brow) * KRST + (16 * t4 + bcol) * 2);
                mma_f16(O[2 * t4], Pa4, v);
                mma_f16(O[2 * t4 + 1], Pa4, v + 2);
            }
        }

        __syncthreads();
        if (kb + 2 < NKV) { issue_kv(kb + 2); CP_COMMIT(); }
    }

    l0 += __shfl_xor_sync(0xffffffffu, l0, 1);
    l0 += __shfl_xor_sync(0xffffffffu, l0, 2);
    l1 += __shfl_xor_sync(0xffffffffu, l1, 1);
    l1 += __shfl_xor_sync(0xffffffffu, l1, 2);

    const int qr0 = q0 + wid * 16 + (lane >> 2);
    const int qr1 = qr0 + 8;
    const float inv0 = masks[b * SS + qr0] / l0;
    const float inv1 = masks[b * SS + qr1] / l1;
#pragma unroll
    for (int nf = 0; nf < 8; nf++) {
        const int col = hc + nf * 8 + (lane & 3) * 2;
        const size_t o0 = (size_t)(b * SS + qr0) * HH + col;
        const size_t o1 = (size_t)(b * SS + qr1) * HH + col;
        float2 r0 = *(const float2*)&query[o0];
        float2 r1 = *(const float2*)&query[o1];
        r0.x = fmaf(O[nf][0], inv0, r0.x);
        r0.y = fmaf(O[nf][1], inv0, r0.y);
        r1.x = fmaf(O[nf][2], inv1, r1.x);
        r1.y = fmaf(O[nf][3], inv1, r1.y);
        *(float2*)&out[o0] = r0;
        *(float2*)&out[o1] = r1;
    }
}

// ---------------------------------------------------------------------------
// Launch topology — QUARTER granularity: each projection GEMM split into 4
// column quarters; attention into 4 head quarters gated on exactly the
// quarters they read. Quarters 0-2 of attention backfill the gemm phase;
// the un-overlappable tail is one 256-CTA attn launch (~half the R13 tail).
// ---------------------------------------------------------------------------
extern "C" void kernel_launch(void* const* d_in, const int* in_sizes, int n_in,
                              void* d_out, int out_size)
{
    (void)in_sizes; (void)n_in; (void)out_size;
    const float* query = (const float*)d_in[0];
    const float* key   = (const float*)d_in[1];
    const float* value = (const float*)d_in[2];
    const float* masks = (const float*)d_in[3];
    const float* Wq    = (const float*)d_in[4];
    const float* bq    = (const float*)d_in[5];
    const float* Wk    = (const float*)d_in[6];
    const float* bk    = (const float*)d_in[7];
    const float* Wv    = (const float*)d_in[8];
    const float* bv    = (const float*)d_in[9];
    float* out = (float*)d_out;

    cudaFuncSetAttribute(gemm_mma, cudaFuncAttributeMaxDynamicSharedMemorySize, GEMM_SMEM);
    cudaFuncSetAttribute(attn_tc, cudaFuncAttributeMaxDynamicSharedMemorySize, ATT_SMEM);

    cudaStream_t s2, s3, s4;
    cudaStreamCreateWithFlags(&s2, cudaStreamNonBlocking);
    cudaStreamCreateWithFlags(&s3, cudaStreamNonBlocking);
    cudaStreamCreateWithFlags(&s4, cudaStreamNonBlocking);

    cudaEvent_t e_cq, e_ck, e_end;
    cudaEvent_t eq[4], ek[4], ev[4];
    cudaEventCreateWithFlags(&e_cq,  cudaEventDisableTiming);
    cudaEventCreateWithFlags(&e_ck,  cudaEventDisableTiming);
    cudaEventCreateWithFlags(&e_end, cudaEventDisableTiming);
    for (int j = 0; j < 4; j++) {
        cudaEventCreateWithFlags(&eq[j], cudaEventDisableTiming);
        cudaEventCreateWithFlags(&ek[j], cudaEventDisableTiming);
        cudaEventCreateWithFlags(&ev[j], cudaEventDisableTiming);
    }

    const int n4x = MTOT * HH / 4;
    const int n4w = HH * HH / 4;
    const int cblocks = (n4x + n4w) / 256;

    const dim3 gq(256 / 128, MTOT / 128);     // (2, 32) = 64 CTAs per N-quarter

    // main: conv_q -> gemm_q quarters
    convert_pair<<<cblocks, 256>>>((const float4*)query, (const float4*)Wq, 0, n4x, n4w);
    cudaEventRecord(e_cq, 0);
    for (int j = 0; j < 4; j++) {
        gemm_mma<<<gq, 256, GEMM_SMEM>>>(bq, 0, j * 256);
        cudaEventRecord(eq[j], 0);
    }

    // s2: conv_k -> gemm_k quarters
    cudaStreamWaitEvent(s2, e_cq, 0);
    convert_pair<<<cblocks, 256, 0, s2>>>((const float4*)key, (const float4*)Wk, 1, n4x, n4w);
    cudaEventRecord(e_ck, s2);
    for (int j = 0; j < 4; j++) {
        gemm_mma<<<gq, 256, GEMM_SMEM, s2>>>(bk, 1, j * 256);
        cudaEventRecord(ek[j], s2);
    }

    // s3: conv_v -> gemm_v quarters
    cudaStreamWaitEvent(s3, e_ck, 0);
    convert_pair<<<cblocks, 256, 0, s3>>>((const float4*)value, (const float4*)Wv, 2, n4x, n4w);
    for (int j = 0; j < 4; j++) {
        gemm_mma<<<gq, 256, GEMM_SMEM, s3>>>(bv, 2, j * 256);
        cudaEventRecord(ev[j], s3);
    }

    // s4: attention head-quarters, each gated on its q/k/v column quarter
    for (int j = 0; j < 4; j++) {
        cudaStreamWaitEvent(s4, eq[j], 0);
        cudaStreamWaitEvent(s4, ek[j], 0);
        cudaStreamWaitEvent(s4, ev[j], 0);
        attn_tc<<<dim3(SS / QB, NHEADS / 4, BB), 128, ATT_SMEM, s4>>>(masks, query, out, j * 4);
    }
    cudaEventRecord(e_end, s4);

    // join everything back onto the origin stream
    cudaStreamWaitEvent(0, e_end, 0);

    cudaEventDestroy(e_cq);
    cudaEventDestroy(e_ck);
    cudaEventDestroy(e_end);
    for (int j = 0; j < 4; j++) {
        cudaEventDestroy(eq[j]);
        cudaEventDestroy(ek[j]);
        cudaEventDestroy(ev[j]);
    }
    cudaStreamDestroy(s2);
    cudaStreamDestroy(s3);
    cudaStreamDestroy(s4);
}

// round 17
// speedup vs baseline: 1.1133x; 1.1133x over previous
#include <cuda_runtime.h>
#include <cuda_fp16.h>
#include <cstdint>

// Problem constants
#define HH     1024
#define BB     4
#define SS     1024
#define NHEADS 16
#define DHEAD  64
#define MTOT   (BB * SS)

// fp16 copies of GEMM inputs.
__device__ __align__(16) __half g_xh[3][(size_t)MTOT * HH];
__device__ __align__(16) __half g_wh[3][(size_t)HH * HH];

// GEMM outputs for attention: Q (pre-scaled by 0.125*log2e), K, V in fp16.
__device__ __align__(16) __half g_qh[(size_t)MTOT * HH];
__device__ __align__(16) __half g_kh[(size_t)MTOT * HH];
__device__ __align__(16) __half g_vh[(size_t)MTOT * HH];

#define SCLQ 0.18033688f   // 0.125 * log2(e)

// ---------------------------------------------------------------------------
// helpers
// ---------------------------------------------------------------------------
static __device__ __forceinline__ uint32_t smem_u32(const void* p) {
    uint32_t a;
    asm("{ .reg .u64 t; cvta.to.shared.u64 t, %1; cvt.u32.u64 %0, t; }"
        : "=r"(a) : "l"(p));
    return a;
}
static __device__ __forceinline__ uint32_t pack2h(float x, float y) {
    __half2 h = __floats2half2_rn(x, y);
    return *reinterpret_cast<uint32_t*>(&h);
}
static __device__ __forceinline__ float2 unpack2h(uint32_t u) {
    __half2 h = *reinterpret_cast<__half2*>(&u);
    return __half22float2(h);
}
static __device__ __forceinline__ void cp16(uint32_t saddr, const void* g) {
    asm volatile("cp.async.cg.shared.global [%0], [%1], 16;"
                 :: "r"(saddr), "l"(g) : "memory");
}
#define CP_COMMIT() asm volatile("cp.async.commit_group;" ::: "memory")

static __device__ __forceinline__ void mma_f16(float* c, const uint32_t* a, const uint32_t* b) {
    asm volatile(
        "mma.sync.aligned.m16n8k16.row.col.f32.f16.f16.f32 "
        "{%0,%1,%2,%3}, {%4,%5,%6,%7}, {%8,%9}, {%0,%1,%2,%3};"
        : "+f"(c[0]), "+f"(c[1]), "+f"(c[2]), "+f"(c[3])
        : "r"(a[0]), "r"(a[1]), "r"(a[2]), "r"(a[3]), "r"(b[0]), "r"(b[1]));
}
// fp16-accumulate variant (QK^T only — logits small, 4 k-steps)
static __device__ __forceinline__ void mma_f16h(uint32_t* c, const uint32_t* a, const uint32_t* b) {
    asm volatile(
        "mma.sync.aligned.m16n8k16.row.col.f16.f16.f16.f16 "
        "{%0,%1}, {%2,%3,%4,%5}, {%6,%7}, {%0,%1};"
        : "+r"(c[0]), "+r"(c[1])
        : "r"(a[0]), "r"(a[1]), "r"(a[2]), "r"(a[3]), "r"(b[0]), "r"(b[1]));
}
static __device__ __forceinline__ void ldsm4(uint32_t* r, uint32_t saddr) {
    asm volatile("ldmatrix.sync.aligned.m8n8.x4.shared.b16 {%0,%1,%2,%3}, [%4];"
                 : "=r"(r[0]), "=r"(r[1]), "=r"(r[2]), "=r"(r[3]) : "r"(saddr));
}
static __device__ __forceinline__ void ldsm4t(uint32_t* r, uint32_t saddr) {
    asm volatile("ldmatrix.sync.aligned.m8n8.x4.trans.shared.b16 {%0,%1,%2,%3}, [%4];"
                 : "=r"(r[0]), "=r"(r[1]), "=r"(r[2]), "=r"(r[3]) : "r"(saddr));
}
static __device__ __forceinline__ float ex2(float x) {
    float y; asm("ex2.approx.f32 %0, %1;" : "=f"(y) : "f"(x)); return y;
}

// ---------------------------------------------------------------------------
// fp32 -> fp16 convert: X range [0, n4x) plus W words [woff4, woff4+n4wp).
// ---------------------------------------------------------------------------
__global__ void convert_pair(const float4* __restrict__ X, const float4* __restrict__ W,
                             int mat, int n4x, int woff4, int n4wp)
{
    const int i = blockIdx.x * 256 + threadIdx.x;
    if (i < n4x) {
        float4 v = X[i];
        ((uint2*)g_xh[mat])[i] = make_uint2(pack2h(v.x, v.y), pack2h(v.z, v.w));
    } else {
        const int j = i - n4x;
        if (j < n4wp) {
            float4 v = W[woff4 + j];
            ((uint2*)g_wh[mat])[woff4 + j] =
                make_uint2(pack2h(v.x, v.y), pack2h(v.z, v.w));
        }
    }
}

// ---------------------------------------------------------------------------
// Tensor-core GEMM (fp16, fp32 acc) — R13 CHAMPION, byte-identical mainloop:
// CTA 128x128, 8 warps (2M x 4N), K staged 64, triple-buffered cp.async ring,
// one __syncthreads per stage. bn0 = column offset (half-N launches).
// ---------------------------------------------------------------------------
#define GST     144
#define GTILE   (128 * GST)
#define GSTAGE  (2 * GTILE)
#define GNST    (HH / 64)
#define GEMM_SMEM (3 * GSTAGE)

__global__ void __launch_bounds__(256, 2) gemm_mma(
    const float* __restrict__ bias, int mat, int bn0)
{
    extern __shared__ char smc[];

    const int tid  = threadIdx.x;
    const int lane = tid & 31;
    const int wid  = tid >> 5;
    const int wm   = wid & 1;
    const int wn   = wid >> 1;
    const int bm   = blockIdx.y * 128;
    const int bn   = bn0 + blockIdx.x * 128;

    const __half* Ah = g_xh[mat] + (size_t)bm * HH;
    const __half* Bh = g_wh[mat] + (size_t)bn * HH;

    const uint32_t smem_base = smem_u32(smc);

    auto issue_stage = [&](int s, int buf) {
        const uint32_t sb = smem_base + (uint32_t)buf * GSTAGE;
        const int k0 = s * 64;
#pragma unroll
        for (int i = 0; i < 4; i++) {
            const int idx = tid + i * 256;
            const int row = idx >> 3;
            const int q   = idx & 7;
            const uint32_t so = (uint32_t)(row * GST + q * 16);
            const size_t   go = (size_t)row * HH + k0 + q * 8;
            cp16(sb + so, Ah + go);
            cp16(sb + GTILE + so, Bh + go);
        }
    };

    float acc[4][4][4];
#pragma unroll
    for (int i = 0; i < 4; i++)
#pragma unroll
        for (int j = 0; j < 4; j++)
#pragma unroll
            for (int k = 0; k < 4; k++) acc[i][j][k] = 0.f;

    issue_stage(0, 0); CP_COMMIT();
    issue_stage(1, 1); CP_COMMIT();

    const int arow = wm * 64 + ((lane >> 3) & 1) * 8 + (lane & 7);
    const int acol = (lane >> 4) * 8;
    const int brow = wn * 32 + (lane & 15);
    const int bcol = (lane >> 4) * 8;

    int cur = 0;
    for (int s = 0; s < GNST; s++) {
        if (s + 1 < GNST) { asm volatile("cp.async.wait_group 1;" ::: "memory"); }
        else              { asm volatile("cp.async.wait_group 0;" ::: "memory"); }
        __syncthreads();

        if (s + 2 < GNST) {
            int nb = cur + 2; if (nb >= 3) nb -= 3;
            issue_stage(s + 2, nb);
            CP_COMMIT();
        }

        const uint32_t sA = smem_base + (uint32_t)cur * GSTAGE;
        const uint32_t sB = sA + GTILE;

#pragma unroll
        for (int t = 0; t < 4; t++) {
            uint32_t Af[4][4], Bf[4][2];
#pragma unroll
            for (int mf = 0; mf < 4; mf++)
                ldsm4(Af[mf], sA + (arow + mf * 16) * GST + (t * 16 + acol) * 2);
#pragma unroll
            for (int np = 0; np < 2; np++) {
                uint32_t kh[4];
                ldsm4(kh, sB + (brow + np * 16) * GST + (t * 16 + bcol) * 2);
                Bf[2 * np][0]     = kh[0]; Bf[2 * np][1]     = kh[2];
                Bf[2 * np + 1][0] = kh[1]; Bf[2 * np + 1][1] = kh[3];
            }
#pragma unroll
            for (int mf = 0; mf < 4; mf++)
#pragma unroll
                for (int nf = 0; nf < 4; nf++)
                    mma_f16(acc[mf][nf], Af[mf], Bf[nf]);
        }

        cur = (cur + 1 == 3) ? 0 : cur + 1;
    }

    const float sc = (mat == 0) ? SCLQ : 1.0f;
    uint32_t* ph = (mat == 0) ? (uint32_t*)g_qh : ((mat == 1) ? (uint32_t*)g_kh : (uint32_t*)g_vh);

#pragma unroll
    for (int nf = 0; nf < 4; nf++) {
        const int col = bn + wn * 32 + nf * 8 + (lane & 3) * 2;
        const float2 bs = *(const float2*)&bias[col];
#pragma unroll
        for (int mf = 0; mf < 4; mf++) {
            const int row0 = bm + wm * 64 + mf * 16 + (lane >> 2);
            float v0 = fmaxf(acc[mf][nf][0] + bs.x, 0.f) * sc;
            float v1 = fmaxf(acc[mf][nf][1] + bs.y, 0.f) * sc;
            float v2 = fmaxf(acc[mf][nf][2] + bs.x, 0.f) * sc;
            float v3 = fmaxf(acc[mf][nf][3] + bs.y, 0.f) * sc;
            ph[((size_t)row0 * HH + col) >> 1]       = pack2h(v0, v1);
            ph[((size_t)(row0 + 8) * HH + col) >> 1] = pack2h(v2, v3);
        }
    }
}

// ---------------------------------------------------------------------------
// Tensor-core flash attention — R13 champion, byte-identical mainloop:
// max-free softmax, kv-tile 64, fp16-acc QK^T (bit-exact repack), fp32-acc
// PV, deferred l-reduction, 4 CTA/SM. n0 = head offset (half launches).
// ---------------------------------------------------------------------------
#define QB      64
#define KRST    144
#define KVT     64
#define KVOFF   (KVT * KRST)
#define KBUF    (2 * KVOFF)
#define ATT_SMEM (2 * KBUF)
#define NKV     (SS / KVT)

__global__ void __launch_bounds__(128, 4) attn_tc(
    const float* __restrict__ masks,
    const float* __restrict__ query,
    float* __restrict__ out,
    int n0)
{
    extern __shared__ char sma[];
    const uint32_t smb = smem_u32(sma);

    const int b    = blockIdx.z;
    const int n    = n0 + blockIdx.y;
    const int q0   = blockIdx.x * QB;
    const int tid  = threadIdx.x;
    const int lane = tid & 31;
    const int wid  = tid >> 5;
    const int hc   = n * DHEAD;

#pragma unroll
    for (int i = 0; i < 4; i++) {
        const int idx = tid + i * 128;
        const int row = idx >> 3, qq = idx & 7;
        cp16(smb + row * KRST + qq * 16,
             g_qh + (size_t)(b * SS + q0 + row) * HH + hc + qq * 8);
    }
    CP_COMMIT();
    asm volatile("cp.async.wait_group 0;" ::: "memory");
    __syncthreads();

    uint32_t qh[4][4];
    {
        const int arow = wid * 16 + ((lane >> 3) & 1) * 8 + (lane & 7);
        const int acol = (lane >> 4) * 8;
#pragma unroll
        for (int t = 0; t < 4; t++)
            ldsm4(qh[t], smb + arow * KRST + (16 * t + acol) * 2);
    }
    __syncthreads();

    auto issue_kv = [&](int s) {
        const uint32_t sb = smb + (uint32_t)((s & 1) * KBUF);
        const size_t tokbase = (size_t)(b * SS + s * KVT);
#pragma unroll
        for (int i = 0; i < 4; i++) {
            const int idx = tid + i * 128;
            const int row = idx >> 3, qq = idx & 7;
            const uint32_t soff = row * KRST + qq * 16;
            const size_t goff = (tokbase + row) * HH + hc + qq * 8;
            cp16(sb + soff, g_kh + goff);
            cp16(sb + KVOFF + soff, g_vh + goff);
        }
    };
    issue_kv(0); CP_COMMIT();
    issue_kv(1); CP_COMMIT();

    float O[8][4];
    float l0 = 0.f, l1 = 0.f;
#pragma unroll
    for (int i = 0; i < 8; i++)
#pragma unroll
        for (int j = 0; j < 4; j++) O[i][j] = 0.f;

    const int brow = lane & 15;
    const int bcol = (lane >> 4) * 8;

    for (int kb = 0; kb < NKV; kb++) {
        if (kb + 1 < NKV) { asm volatile("cp.async.wait_group 1;" ::: "memory"); }
        else              { asm volatile("cp.async.wait_group 0;" ::: "memory"); }
        __syncthreads();

        const uint32_t sb = smb + (uint32_t)((kb & 1) * KBUF);

        uint32_t Sh[8][2];
#pragma unroll
        for (int i = 0; i < 8; i++) { Sh[i][0] = 0u; Sh[i][1] = 0u; }

#pragma unroll
        for (int t = 0; t < 4; t++) {
#pragma unroll
            for (int j = 0; j < 4; j++) {
                uint32_t kh[4], bf[2];
                ldsm4(kh, sb + (16 * j + brow) * KRST + (16 * t + bcol) * 2);
                bf[0] = kh[0]; bf[1] = kh[2];
                mma_f16h(Sh[2 * j], qh[t], bf);
                bf[0] = kh[1]; bf[1] = kh[3];
                mma_f16h(Sh[2 * j + 1], qh[t], bf);
            }
        }

#pragma unroll
        for (int i = 0; i < 8; i++) {
            float2 a = unpack2h(Sh[i][0]);
            float2 c = unpack2h(Sh[i][1]);
            float e0 = ex2(a.x), e1 = ex2(a.y);
            float e2 = ex2(c.x), e3 = ex2(c.y);
            l0 += e0 + e1;
            l1 += e2 + e3;
            Sh[i][0] = pack2h(e0, e1);
            Sh[i][1] = pack2h(e2, e3);
        }

#pragma unroll
        for (int i = 0; i < 4; i++) {
            uint32_t Pa4[4] = {Sh[2 * i][0], Sh[2 * i][1],
                               Sh[2 * i + 1][0], Sh[2 * i + 1][1]};
#pragma unroll
            for (int t4 = 0; t4 < 4; t4++) {
                uint32_t v[4];
                ldsm4t(v, sb + KVOFF + (16 * i + brow) * KRST + (16 * t4 + bcol) * 2);
                mma_f16(O[2 * t4], Pa4, v);
                mma_f16(O[2 * t4 + 1], Pa4, v + 2);
            }
        }

        __syncthreads();
        if (kb + 2 < NKV) { issue_kv(kb + 2); CP_COMMIT(); }
    }

    l0 += __shfl_xor_sync(0xffffffffu, l0, 1);
    l0 += __shfl_xor_sync(0xffffffffu, l0, 2);
    l1 += __shfl_xor_sync(0xffffffffu, l1, 1);
    l1 += __shfl_xor_sync(0xffffffffu, l1, 2);

    const int qr0 = q0 + wid * 16 + (lane >> 2);
    const int qr1 = qr0 + 8;
    const float inv0 = masks[b * SS + qr0] / l0;
    const float inv1 = masks[b * SS + qr1] / l1;
#pragma unroll
    for (int nf = 0; nf < 8; nf++) {
        const int col = hc + nf * 8 + (lane & 3) * 2;
        const size_t o0 = (size_t)(b * SS + qr0) * HH + col;
        const size_t o1 = (size_t)(b * SS + qr1) * HH + col;
        float2 r0 = *(const float2*)&query[o0];
        float2 r1 = *(const float2*)&query[o1];
        r0.x = fmaf(O[nf][0], inv0, r0.x);
        r0.y = fmaf(O[nf][1], inv0, r0.y);
        r1.x = fmaf(O[nf][2], inv1, r1.x);
        r1.y = fmaf(O[nf][3], inv1, r1.y);
        *(float2*)&out[o0] = r0;
        *(float2*)&out[o1] = r1;
    }
}

// ---------------------------------------------------------------------------
// Launch topology — R13 champion (half granularity) + off-critical-path
// conv of Wq-hi. FIX vs R16: every side stream is forked from the capturing
// stream via a root event BEFORE its first launch (stream-capture rule).
//   main: [root] conv_q1 → gemm_q_lo → (wait conv_q2) gemm_q_hi ... attn_hi
//   s4:   (root) conv_q2 ................. (all lo done) attn_lo
//   s2:   (conv_q1) conv_k → gemm_k_lo → gemm_k_hi
//   s3:   (conv_k)  conv_v → gemm_v_lo → gemm_v_hi
// ---------------------------------------------------------------------------
extern "C" void kernel_launch(void* const* d_in, const int* in_sizes, int n_in,
                              void* d_out, int out_size)
{
    (void)in_sizes; (void)n_in; (void)out_size;
    const float* query = (const float*)d_in[0];
    const float* key   = (const float*)d_in[1];
    const float* value = (const float*)d_in[2];
    const float* masks = (const float*)d_in[3];
    const float* Wq    = (const float*)d_in[4];
    const float* bq    = (const float*)d_in[5];
    const float* Wk    = (const float*)d_in[6];
    const float* bk    = (const float*)d_in[7];
    const float* Wv    = (const float*)d_in[8];
    const float* bv    = (const float*)d_in[9];
    float* out = (float*)d_out;

    cudaFuncSetAttribute(gemm_mma, cudaFuncAttributeMaxDynamicSharedMemorySize, GEMM_SMEM);
    cudaFuncSetAttribute(attn_tc, cudaFuncAttributeMaxDynamicSharedMemorySize, ATT_SMEM);

    cudaStream_t s2, s3, s4;
    cudaStreamCreateWithFlags(&s2, cudaStreamNonBlocking);
    cudaStreamCreateWithFlags(&s3, cudaStreamNonBlocking);
    cudaStreamCreateWithFlags(&s4, cudaStreamNonBlocking);
    cudaEvent_t e_root, e_cq1, e_cq2, e_ck;
    cudaEvent_t e_qlo, e_klo, e_vlo, e_khi, e_vhi, e_alo;
    cudaEventCreateWithFlags(&e_root, cudaEventDisableTiming);
    cudaEventCreateWithFlags(&e_cq1, cudaEventDisableTiming);
    cudaEventCreateWithFlags(&e_cq2, cudaEventDisableTiming);
    cudaEventCreateWithFlags(&e_ck,  cudaEventDisableTiming);
    cudaEventCreateWithFlags(&e_qlo, cudaEventDisableTiming);
    cudaEventCreateWithFlags(&e_klo, cudaEventDisableTiming);
    cudaEventCreateWithFlags(&e_vlo, cudaEventDisableTiming);
    cudaEventCreateWithFlags(&e_khi, cudaEventDisableTiming);
    cudaEventCreateWithFlags(&e_vhi, cudaEventDisableTiming);
    cudaEventCreateWithFlags(&e_alo, cudaEventDisableTiming);

    const int n4x  = MTOT * HH / 4;          // 1,048,576 float4
    const int n4w  = HH * HH / 4;            //   262,144 float4
    const int n4wh = n4w / 2;                //   131,072 float4 (W half)
    const int cblocks  = (n4x + n4w) / 256;
    const int cblocks1 = (n4x + n4wh) / 256;
    const int cblocks2 = n4wh / 256;

    const dim3 ghalf(HH / 256, MTOT / 128);  // (4, 32) = 128 CTAs per N-half

    // Fork root: all side streams must descend from the capturing stream.
    cudaEventRecord(e_root, 0);

    // s4: conv_q part 2 (Wq rows 512..1023) — off the critical path
    cudaStreamWaitEvent(s4, e_root, 0);
    convert_pair<<<cblocks2, 256, 0, s4>>>((const float4*)query, (const float4*)Wq,
                                           0, 0, n4wh, n4wh);
    cudaEventRecord(e_cq2, s4);

    // main: conv_q part 1 (Xq + Wq rows 0..511) -> gemm_q lo, then hi
    convert_pair<<<cblocks1, 256>>>((const float4*)query, (const float4*)Wq,
                                    0, n4x, 0, n4wh);
    cudaEventRecord(e_cq1, 0);
    gemm_mma<<<ghalf, 256, GEMM_SMEM>>>(bq, 0, 0);
    cudaEventRecord(e_qlo, 0);
    cudaStreamWaitEvent(0, e_cq2, 0);
    gemm_mma<<<ghalf, 256, GEMM_SMEM>>>(bq, 0, 512);

    // s2: conv_k -> gemm_k lo, hi
    cudaStreamWaitEvent(s2, e_cq1, 0);
    convert_pair<<<cblocks, 256, 0, s2>>>((const float4*)key, (const float4*)Wk,
                                          1, n4x, 0, n4w);
    cudaEventRecord(e_ck, s2);
    gemm_mma<<<ghalf, 256, GEMM_SMEM, s2>>>(bk, 1, 0);
    cudaEventRecord(e_klo, s2);
    gemm_mma<<<ghalf, 256, GEMM_SMEM, s2>>>(bk, 1, 512);
    cudaEventRecord(e_khi, s2);

    // s3: conv_v -> gemm_v lo, hi
    cudaStreamWaitEvent(s3, e_ck, 0);
    convert_pair<<<cblocks, 256, 0, s3>>>((const float4*)value, (const float4*)Wv,
                                          2, n4x, 0, n4w);
    gemm_mma<<<ghalf, 256, GEMM_SMEM, s3>>>(bv, 2, 0);
    cudaEventRecord(e_vlo, s3);
    gemm_mma<<<ghalf, 256, GEMM_SMEM, s3>>>(bv, 2, 512);
    cudaEventRecord(e_vhi, s3);

    // s4: attn for heads 0-7 as soon as lo columns of q/k/v are done
    cudaStreamWaitEvent(s4, e_qlo, 0);
    cudaStreamWaitEvent(s4, e_klo, 0);
    cudaStreamWaitEvent(s4, e_vlo, 0);
    attn_tc<<<dim3(SS / QB, NHEADS / 2, BB), 128, ATT_SMEM, s4>>>(masks, query, out, 0);
    cudaEventRecord(e_alo, s4);

    // main: attn for heads 8-15 after hi gemms; join attn_lo at the end
    cudaStreamWaitEvent(0, e_khi, 0);
    cudaStreamWaitEvent(0, e_vhi, 0);
    attn_tc<<<dim3(SS / QB, NHEADS / 2, BB), 128, ATT_SMEM>>>(masks, query, out, 8);
    cudaStreamWaitEvent(0, e_alo, 0);

    cudaEventDestroy(e_root);
    cudaEventDestroy(e_cq1);
    cudaEventDestroy(e_cq2);
    cudaEventDestroy(e_ck);
    cudaEventDestroy(e_qlo);
    cudaEventDestroy(e_klo);
    cudaEventDestroy(e_vlo);
    cudaEventDestroy(e_khi);
    cudaEventDestroy(e_vhi);
    cudaEventDestroy(e_alo);
    cudaStreamDestroy(s2);
    cudaStreamDestroy(s3);
    cudaStreamDestroy(s4);
}